// round 3
// baseline (speedup 1.0000x reference)
#include <cuda_runtime.h>
#include <cuda_bf16.h>
#include <float.h>

// Problem constants
#define B_  16
#define C_  256
#define H_  128
#define W_  128
#define HW_ (H_ * W_)            // 16384
#define HW4_ (HW_ / 4)           // 4096
#define KSZ 7
#define PAD 3

#define GROUP_B 2                // batches per group (32 MiB of x -> L2 resident)
#define NGROUP (B_ / GROUP_B)    // 8
#define CSLICE 16                // channel slices per pixel
#define CH_PER (C_ / CSLICE)     // 16 channels per thread
#define PXB 16                   // float4 pixel-groups per block

// Scratch maps (per batch, per pixel)
__device__ float g_max[B_ * HW_];   // 1 MiB
__device__ float g_avg[B_ * HW_];   // 1 MiB
__device__ float g_gate[B_ * HW_];  // 1 MiB

// ---------------------------------------------------------------------------
// K1: channel reduction for one 2-batch group, channel-split 16-way with
// in-block shared-memory combine. Block = 16 pixel-groups x 16 channel-slices.
// Grid per group = 2*4096/16 = 512 blocks -> good SM balance (~3.5 CTA/SM).
// ---------------------------------------------------------------------------
__global__ void __launch_bounds__(256) reduce_kernel(const float* __restrict__ x, int b0) {
    const int px = threadIdx.x & (PXB - 1);   // pixel-group within block
    const int cs = threadIdx.x >> 4;          // channel slice 0..15

    const int pb = blockIdx.x * PXB;          // pixel-group index within group [0, GROUP_B*HW4_)
    const int b_local = pb >> 12;             // / HW4_
    const int pg = (pb & (HW4_ - 1)) + px;
    const int b = b0 + b_local;

    const float4* __restrict__ xb =
        reinterpret_cast<const float4*>(x) + ((size_t)(b * C_ + cs * CH_PER)) * HW4_ + pg;

    float4 mx = make_float4(-FLT_MAX, -FLT_MAX, -FLT_MAX, -FLT_MAX);
    float4 sm = make_float4(0.f, 0.f, 0.f, 0.f);

    // 16 channels per thread, two batches of 8 outstanding loads (MLP=8)
    float4 v[8];
    #pragma unroll
    for (int u = 0; u < 8; u++) v[u] = xb[(size_t)u * HW4_];
    #pragma unroll
    for (int u = 0; u < 8; u++) {
        mx.x = fmaxf(mx.x, v[u].x); sm.x += v[u].x;
        mx.y = fmaxf(mx.y, v[u].y); sm.y += v[u].y;
        mx.z = fmaxf(mx.z, v[u].z); sm.z += v[u].z;
        mx.w = fmaxf(mx.w, v[u].w); sm.w += v[u].w;
    }
    #pragma unroll
    for (int u = 0; u < 8; u++) v[u] = xb[(size_t)(u + 8) * HW4_];
    #pragma unroll
    for (int u = 0; u < 8; u++) {
        mx.x = fmaxf(mx.x, v[u].x); sm.x += v[u].x;
        mx.y = fmaxf(mx.y, v[u].y); sm.y += v[u].y;
        mx.z = fmaxf(mx.z, v[u].z); sm.z += v[u].z;
        mx.w = fmaxf(mx.w, v[u].w); sm.w += v[u].w;
    }

    // Shared-memory combine across the 16 channel slices
    __shared__ float4 s_mx[256];
    __shared__ float4 s_sm[256];
    s_mx[threadIdx.x] = mx;
    s_sm[threadIdx.x] = sm;

    #pragma unroll
    for (int sh = 8; sh >= 1; sh >>= 1) {
        __syncthreads();
        if (threadIdx.x < sh * PXB) {
            float4 omx = s_mx[threadIdx.x + sh * PXB];
            float4 osm = s_sm[threadIdx.x + sh * PXB];
            float4 a = s_mx[threadIdx.x];
            float4 s = s_sm[threadIdx.x];
            a.x = fmaxf(a.x, omx.x); s.x += osm.x;
            a.y = fmaxf(a.y, omx.y); s.y += osm.y;
            a.z = fmaxf(a.z, omx.z); s.z += osm.z;
            a.w = fmaxf(a.w, omx.w); s.w += osm.w;
            s_mx[threadIdx.x] = a;
            s_sm[threadIdx.x] = s;
        }
    }

    if (threadIdx.x < PXB) {
        float4 fm = s_mx[threadIdx.x];
        float4 fs = s_sm[threadIdx.x];
        const float inv_c = 1.0f / (float)C_;
        fs.x *= inv_c; fs.y *= inv_c; fs.z *= inv_c; fs.w *= inv_c;
        reinterpret_cast<float4*>(g_max)[b * HW4_ + pg] = fm;
        reinterpret_cast<float4*>(g_avg)[b * HW4_ + pg] = fs;
    }
}

// ---------------------------------------------------------------------------
// K2: 7x7 conv over [max, avg] + bias + hsigmoid -> gate map. One thread per
// pixel, for one 2-batch group (32768 threads -> 128 blocks). All L2-resident.
// ---------------------------------------------------------------------------
__global__ void __launch_bounds__(256) gate_kernel(const float* __restrict__ conv_w,
                                                   const float* __restrict__ conv_b,
                                                   int b0) {
    __shared__ float sw[2 * KSZ * KSZ];  // 98 weights
    __shared__ float sbias;
    if (threadIdx.x < 2 * KSZ * KSZ) sw[threadIdx.x] = conv_w[threadIdx.x];
    if (threadIdx.x == 0) sbias = conv_b[0];
    __syncthreads();

    int tid = blockIdx.x * 256 + threadIdx.x;     // 0 .. GROUP_B*HW_-1 (32768)
    int b = b0 + (tid >> 14);                      // / HW_
    int p = tid & (HW_ - 1);
    int h = p >> 7;                                // / W_
    int w = p & (W_ - 1);

    const float* __restrict__ mp = g_max + b * HW_;
    const float* __restrict__ ap = g_avg + b * HW_;

    float acc = sbias;
    #pragma unroll
    for (int kh = 0; kh < KSZ; kh++) {
        int hh = h + kh - PAD;
        if (hh < 0 || hh >= H_) continue;
        int rowoff = hh * W_;
        #pragma unroll
        for (int kw = 0; kw < KSZ; kw++) {
            int ww = w + kw - PAD;
            if (ww < 0 || ww >= W_) continue;
            int q = rowoff + ww;
            acc = fmaf(sw[kh * KSZ + kw],      mp[q], acc);
            acc = fmaf(sw[49 + kh * KSZ + kw], ap[q], acc);
        }
    }

    float g = fminf(fmaxf(acc + 3.0f, 0.0f), 6.0f) * (1.0f / 6.0f);
    g_gate[b * HW_ + p] = g;
}

// ---------------------------------------------------------------------------
// K3: out = x * gate for one 2-batch group. x re-read should hit L2 (just
// loaded by K1). __ldcs = evict-first read (last use), __stcs = streaming
// store so output doesn't evict not-yet-read x from L2.
// ---------------------------------------------------------------------------
__global__ void __launch_bounds__(256) mul_kernel(const float* __restrict__ x,
                                                  float* __restrict__ out,
                                                  int b0) {
    int i = blockIdx.x * 256 + threadIdx.x;       // 0 .. GROUP_B*C_*HW4_-1 (2M)
    int pg = i & (HW4_ - 1);
    int bl = i >> 20;                              // / (C_*HW4_) = /2^20
    size_t i4 = (size_t)b0 * (C_ * HW4_) + i;

    float4 xv = __ldcs(reinterpret_cast<const float4*>(x) + i4);
    float4 gv = reinterpret_cast<const float4*>(g_gate)[(b0 + bl) * HW4_ + pg];

    float4 ov;
    ov.x = xv.x * gv.x;
    ov.y = xv.y * gv.y;
    ov.z = xv.z * gv.z;
    ov.w = xv.w * gv.w;
    __stcs(reinterpret_cast<float4*>(out) + i4, ov);
}

// ---------------------------------------------------------------------------
extern "C" void kernel_launch(void* const* d_in, const int* in_sizes, int n_in,
                              void* d_out, int out_size) {
    const float* x      = (const float*)d_in[0];  // [16,256,128,128]
    const float* conv_w = (const float*)d_in[1];  // [1,2,7,7] = 98 floats
    const float* conv_b = (const float*)d_in[2];  // [1]
    float* out = (float*)d_out;

    for (int g = 0; g < NGROUP; g++) {
        int b0 = g * GROUP_B;
        // K1: 2 batches x 4096 pixel-groups / 16 per block = 512 blocks
        reduce_kernel<<<(GROUP_B * HW4_) / PXB, 256>>>(x, b0);
        // K2: 2 batches x 16384 pixels = 32768 threads -> 128 blocks
        gate_kernel<<<(GROUP_B * HW_) / 256, 256>>>(conv_w, conv_b, b0);
        // K3: 2 batches x 256 ch x 4096 groups = 2M threads -> 8192 blocks
        mul_kernel<<<(GROUP_B * C_ * HW4_) / 256, 256>>>(x, out, b0);
    }
}

// round 5
// speedup vs baseline: 1.1922x; 1.1922x over previous
#include <cuda_runtime.h>
#include <cuda_bf16.h>
#include <float.h>

// Problem constants
#define B_   16
#define C_   256
#define H_   128
#define W_   128
#define HW_  (H_ * W_)           // 16384
#define HW4_ (HW_ / 4)           // 4096 float4 pixel-groups per batch
#define KSZ  7
#define PAD  3

#define NB        512            // persistent grid size (<= 4 CTAs/SM * 148 SMs)
#define GROUP_B   2              // batches per chunk (32 MiB of x, L2-resident)
#define NCHUNK    (B_ / GROUP_B) // 8
#define TILE_PG   16             // pixel-groups per tile (64 pixels)
#define TILES_PER_BATCH (HW4_ / TILE_PG)   // 256
#define TILES_PER_CHUNK (GROUP_B * TILES_PER_BATCH)  // 512 == NB

// Scratch maps (per batch, per pixel) - written phase1, read phase2, disjoint per chunk
__device__ float g_max[B_ * HW_];   // 1 MiB
__device__ float g_avg[B_ * HW_];   // 1 MiB

// Grid barrier state
__device__ unsigned g_bar_cnt = 0;
__device__ volatile unsigned g_bar_gen = 0;

__device__ __forceinline__ void grid_barrier() {
    __syncthreads();
    if (threadIdx.x == 0) {
        unsigned gen = g_bar_gen;
        __threadfence();                       // make my phase-1 stores visible
        if (atomicAdd(&g_bar_cnt, 1u) == NB - 1u) {
            g_bar_cnt = 0u;
            __threadfence();                   // count reset visible before release
            g_bar_gen = gen + 1u;              // release (volatile store)
        } else {
            while (g_bar_gen == gen) { __nanosleep(64); }
            __threadfence();
        }
    }
    __syncthreads();
}

// ---------------------------------------------------------------------------
// One persistent kernel: for each 2-batch chunk
//   phase1: channel max+mean reduction (x -> L2; maps -> L2)
//   barrier
//   phase2: per pixel-tile: 7x7 conv + hsigmoid gates (smem), then multiply
//           all 256 channels (x re-read from L2, streaming store out)
// ---------------------------------------------------------------------------
__global__ void __launch_bounds__(256, 4)
fused_kernel(const float* __restrict__ x,
             const float* __restrict__ conv_w,
             const float* __restrict__ conv_b,
             float* __restrict__ out) {
    __shared__ float4 s_mx[256];
    __shared__ float4 s_sm[256];
    __shared__ float  s_w[2 * KSZ * KSZ];
    __shared__ __align__(16) float s_gate[TILE_PG * 4];  // 64 gates
    __shared__ float  s_bias;

    if (threadIdx.x < 2 * KSZ * KSZ) s_w[threadIdx.x] = conv_w[threadIdx.x];
    if (threadIdx.x == 0) s_bias = conv_b[0];
    // (s_w/s_bias first used after the first grid_barrier's __syncthreads)

    const int t   = blockIdx.x;            // 0..511, one tile per phase
    const int b_l = t >> 8;                // local batch within chunk (0/1)
    const int pg0 = (t & 255) * TILE_PG;   // first pixel-group of tile

    for (int chunk = 0; chunk < NCHUNK; chunk++) {
        const int b = chunk * GROUP_B + b_l;

        // ================= Phase 1: channel reduction for this tile ========
        {
            const int px = threadIdx.x & 15;   // pixel-group within tile
            const int cs = threadIdx.x >> 4;   // channel slice 0..15 (16 ch each)
            const int pg = pg0 + px;

            const float4* __restrict__ xb =
                reinterpret_cast<const float4*>(x)
                + ((size_t)(b * C_ + cs * 16)) * HW4_ + pg;

            float4 mx = make_float4(-FLT_MAX, -FLT_MAX, -FLT_MAX, -FLT_MAX);
            float4 sm = make_float4(0.f, 0.f, 0.f, 0.f);

            #pragma unroll
            for (int grp = 0; grp < 4; grp++) {      // 4 groups of 4 channels (MLP=4)
                float4 v[4];
                #pragma unroll
                for (int u = 0; u < 4; u++)
                    v[u] = xb[(size_t)(grp * 4 + u) * HW4_];
                #pragma unroll
                for (int u = 0; u < 4; u++) {
                    mx.x = fmaxf(mx.x, v[u].x); sm.x += v[u].x;
                    mx.y = fmaxf(mx.y, v[u].y); sm.y += v[u].y;
                    mx.z = fmaxf(mx.z, v[u].z); sm.z += v[u].z;
                    mx.w = fmaxf(mx.w, v[u].w); sm.w += v[u].w;
                }
            }

            s_mx[threadIdx.x] = mx;
            s_sm[threadIdx.x] = sm;

            #pragma unroll
            for (int sh = 8; sh >= 1; sh >>= 1) {
                __syncthreads();
                if (threadIdx.x < sh * 16) {
                    float4 omx = s_mx[threadIdx.x + sh * 16];
                    float4 osm = s_sm[threadIdx.x + sh * 16];
                    float4 a = s_mx[threadIdx.x];
                    float4 s = s_sm[threadIdx.x];
                    a.x = fmaxf(a.x, omx.x); s.x += osm.x;
                    a.y = fmaxf(a.y, omx.y); s.y += osm.y;
                    a.z = fmaxf(a.z, omx.z); s.z += osm.z;
                    a.w = fmaxf(a.w, omx.w); s.w += osm.w;
                    s_mx[threadIdx.x] = a;
                    s_sm[threadIdx.x] = s;
                }
            }

            if (threadIdx.x < 16) {
                float4 fm = s_mx[threadIdx.x];
                float4 fs = s_sm[threadIdx.x];
                const float inv_c = 1.0f / (float)C_;
                fs.x *= inv_c; fs.y *= inv_c; fs.z *= inv_c; fs.w *= inv_c;
                reinterpret_cast<float4*>(g_max)[b * HW4_ + pg0 + threadIdx.x] = fm;
                reinterpret_cast<float4*>(g_avg)[b * HW4_ + pg0 + threadIdx.x] = fs;
            }
        }

        // ============== barrier: all maps of this chunk complete ===========
        grid_barrier();

        // ================= Phase 2: gates + channel-broadcast multiply =====
        {
            // 2a: threads 0..63 compute the tile's 64 gates (7x7 conv, hsigmoid)
            if (threadIdx.x < TILE_PG * 4) {
                const int p = pg0 * 4 + threadIdx.x;
                const int h = p >> 7;
                const int w = p & (W_ - 1);
                const float* __restrict__ mp = g_max + b * HW_;
                const float* __restrict__ ap = g_avg + b * HW_;

                float acc = s_bias;
                #pragma unroll
                for (int kh = 0; kh < KSZ; kh++) {
                    int hh = h + kh - PAD;
                    if (hh < 0 || hh >= H_) continue;
                    int rowoff = hh * W_;
                    #pragma unroll
                    for (int kw = 0; kw < KSZ; kw++) {
                        int ww = w + kw - PAD;
                        if (ww < 0 || ww >= W_) continue;
                        int q = rowoff + ww;
                        acc = fmaf(s_w[kh * KSZ + kw],      mp[q], acc);
                        acc = fmaf(s_w[49 + kh * KSZ + kw], ap[q], acc);
                    }
                }
                s_gate[threadIdx.x] =
                    fminf(fmaxf(acc + 3.0f, 0.0f), 6.0f) * (1.0f / 6.0f);
            }
            __syncthreads();

            // 2b: multiply all 256 channels for this tile.
            // Thread layout: pg_l = tid&15 (coalesced), c0 = tid>>4; 16 ch/thread.
            const int pg_l = threadIdx.x & 15;
            const int c0   = threadIdx.x >> 4;
            const int pg   = pg0 + pg_l;
            const float4 gv = reinterpret_cast<float4*>(s_gate)[pg_l];

            const float4* __restrict__ xb =
                reinterpret_cast<const float4*>(x) + ((size_t)b * C_) * HW4_ + pg;
            float4* __restrict__ ob =
                reinterpret_cast<float4*>(out) + ((size_t)b * C_) * HW4_ + pg;

            #pragma unroll
            for (int grp = 0; grp < 4; grp++) {      // 4 groups of 4 channels (MLP=4)
                float4 v[4];
                int cbase = c0 + grp * 64;           // channels c0 + {0,16,32,48} + grp*64
                #pragma unroll
                for (int u = 0; u < 4; u++)
                    v[u] = __ldcs(xb + (size_t)(cbase + u * 16) * HW4_);
                #pragma unroll
                for (int u = 0; u < 4; u++) {
                    float4 ov;
                    ov.x = v[u].x * gv.x;
                    ov.y = v[u].y * gv.y;
                    ov.z = v[u].z * gv.z;
                    ov.w = v[u].w * gv.w;
                    __stcs(ob + (size_t)(cbase + u * 16) * HW4_, ov);
                }
            }
        }
        // No barrier needed here: next chunk's phase1 touches disjoint map
        // regions; the next grid_barrier orders everything else.
    }
}

// ---------------------------------------------------------------------------
extern "C" void kernel_launch(void* const* d_in, const int* in_sizes, int n_in,
                              void* d_out, int out_size) {
    const float* x      = (const float*)d_in[0];  // [16,256,128,128]
    const float* conv_w = (const float*)d_in[1];  // [1,2,7,7] = 98 floats
    const float* conv_b = (const float*)d_in[2];  // [1]
    float* out = (float*)d_out;

    fused_kernel<<<NB, 256>>>(x, conv_w, conv_b, out);
}